// round 15
// baseline (speedup 1.0000x reference)
#include <cuda_runtime.h>

// Problem constants (fixed shapes from reference_code)
#define E_    3
#define QE_   60000
#define P_    40
#define H_    20
#define NIMG_ 1800
#define Q_    (E_ * QE_)        // 180000 atoms
#define NNZ_  14400000
#define AB    256               // atoms per block
#define NB    704               // ceil(Q_/AB)
#define XSTR  44                // padded smem row stride (floats) for staged fps

// Scratch (static device globals — sanctioned)
__device__ float g_dE[(size_t)Q_ * P_];        // NEGATED dE/dFP, sorted order, 28.8 MB
__device__ int   g_hist[(size_t)NIMG_ * NB];
__device__ int   g_key_total[NIMG_];
__device__ int   g_key_base[NIMG_];

__device__ __forceinline__ float tanh_fast(float x) {
    float y;
    asm("tanh.approx.f32 %0, %1;" : "=f"(y) : "f"(x));
    return y;
}

// ---- packed f32x2 helpers (Blackwell FFMA2 via PTX) ----
__device__ __forceinline__ unsigned long long pk2(float a, float b) {
    unsigned long long d;
    asm("mov.b64 %0, {%1, %2};" : "=l"(d) : "f"(a), "f"(b));
    return d;
}
__device__ __forceinline__ void upk2(unsigned long long d, float& a, float& b) {
    unsigned x, y;
    asm("mov.b64 {%0, %1}, %2;" : "=r"(x), "=r"(y) : "l"(d));
    a = __uint_as_float(x);
    b = __uint_as_float(y);
}
__device__ __forceinline__ unsigned long long fma2(
    unsigned long long a, unsigned long long b, unsigned long long c) {
    unsigned long long d;
    asm("fma.rn.f32x2 %0, %1, %2, %3;" : "=l"(d) : "l"(a), "l"(b), "l"(c));
    return d;
}

// ---------------------------------------------------------------------------
// Histogram of image_idx, fused with zeroing of the output buffer (R8 form).
// ---------------------------------------------------------------------------
__global__ void k_hist(const int* __restrict__ idx,
                       float* __restrict__ out, int out_n) {
    __shared__ int h[NIMG_];
    for (int k = threadIdx.x; k < NIMG_; k += blockDim.x) h[k] = 0;

    for (int i = blockIdx.x * AB + threadIdx.x; i < out_n; i += NB * AB)
        out[i] = 0.0f;
    __syncthreads();

    int a = blockIdx.x * AB + threadIdx.x;
    if (a < Q_) atomicAdd(&h[idx[a]], 1);
    __syncthreads();
    for (int k = threadIdx.x; k < NIMG_; k += blockDim.x)
        g_hist[(size_t)k * NB + blockIdx.x] = h[k];
}

// ---------------------------------------------------------------------------
// Per-key exclusive scan over blocks: warp-shuffle 2-level scan.
// ---------------------------------------------------------------------------
__global__ void k_scan_blocks() {
    __shared__ int wsum[22];
    int k = blockIdx.x, t = threadIdx.x;
    int lane = t & 31, w = t >> 5;
    int v = g_hist[(size_t)k * NB + t];
    int s = v;
    #pragma unroll
    for (int o = 1; o < 32; o <<= 1) {
        int x = __shfl_up_sync(0xFFFFFFFFu, s, o);
        if (lane >= o) s += x;
    }
    if (lane == 31) wsum[w] = s;
    __syncthreads();
    if (w == 0) {
        int ws = (lane < 22) ? wsum[lane] : 0;
        #pragma unroll
        for (int o = 1; o < 32; o <<= 1) {
            int x = __shfl_up_sync(0xFFFFFFFFu, ws, o);
            if (lane >= o) ws += x;
        }
        if (lane < 22) wsum[lane] = ws;
    }
    __syncthreads();
    int incl = ((w > 0) ? wsum[w - 1] : 0) + s;
    g_hist[(size_t)k * NB + t] = incl - v;   // exclusive
    if (t == NB - 1) g_key_total[k] = incl;
}

// ---------------------------------------------------------------------------
// Exclusive scan over 1800 key totals (2 elems/thread, shuffle scan).
// ---------------------------------------------------------------------------
__global__ void k_scan_keys() {
    __shared__ int wsum[32];
    int t = threadIdx.x, lane = t & 31, w = t >> 5;
    int i0 = 2 * t, i1 = 2 * t + 1;
    int v0 = (i0 < NIMG_) ? g_key_total[i0] : 0;
    int v1 = (i1 < NIMG_) ? g_key_total[i1] : 0;
    int p = v0 + v1, s = p;
    #pragma unroll
    for (int o = 1; o < 32; o <<= 1) {
        int x = __shfl_up_sync(0xFFFFFFFFu, s, o);
        if (lane >= o) s += x;
    }
    if (lane == 31) wsum[w] = s;
    __syncthreads();
    if (w == 0) {
        int ws = wsum[lane];
        #pragma unroll
        for (int o = 1; o < 32; o <<= 1) {
            int x = __shfl_up_sync(0xFFFFFFFFu, ws, o);
            if (lane >= o) ws += x;
        }
        wsum[lane] = ws;
    }
    __syncthreads();
    int excl = ((w > 0) ? wsum[w - 1] : 0) + s - p;
    if (i0 < NIMG_) g_key_base[i0] = excl;
    if (i1 < NIMG_) g_key_base[i1] = excl + v0;
}

// ---------------------------------------------------------------------------
// Fused: stable rank + MLP fwd + input-grad + energy scatter.
// R14 f32x2 core + fps staged through shared memory: the block's 256
// contiguous atom rows are loaded with COALESCED float4 LDGs (4 wf/instr
// vs 32 for the old strided per-thread loads) into a stride-44 padded tile
// (16B-aligned, conflict-free phases), then consumed as float4 LDS.
// ---------------------------------------------------------------------------
__global__ void __launch_bounds__(AB, 3) k_mlp(
    const float* __restrict__ fps, const float* __restrict__ W1,
    const float* __restrict__ b1,  const float* __restrict__ W2,
    const float* __restrict__ b2,  const float* __restrict__ W3,
    const float* __restrict__ b3,  const int* __restrict__ idx,
    float* __restrict__ energy)
{
    __shared__ __align__(16) float sW1 [E_ * P_ * H_];   // [P][H] per element
    __shared__ __align__(16) float sW2 [E_ * H_ * H_];   // [h][j]
    __shared__ __align__(16) float sW2T[E_ * H_ * H_];   // [j][h]
    __shared__ __align__(8)  float sB1[E_ * H_];
    __shared__ float sB2[E_ * H_];
    __shared__ float sW3[E_ * H_];
    __shared__ float sB3[E_];
    __shared__ int   skey[AB];
    extern __shared__ __align__(16) float sX[];   // AB * XSTR floats (45056 B)

    int t = threadIdx.x;
    int a = blockIdx.x * AB + t;
    bool valid = (a < Q_);

    // early: key + the two divergent pos-gathers (latency hidden by staging)
    int key = valid ? idx[a] : -1;
    skey[t] = key;
    int kb = 0, hb = 0;
    if (valid) {
        kb = g_key_base[key];
        hb = g_hist[(size_t)key * NB + blockIdx.x];
    }

    // stage fps tile: 2560 float4, coalesced, into padded stride-44 rows
    {
        const float4* gx = (const float4*)(fps + (size_t)blockIdx.x * AB * P_);
        int gbase = blockIdx.x * (AB * P_ / 4);
        #pragma unroll
        for (int it = 0; it < P_ / 4; it++) {
            int i4 = it * AB + t;                  // 0 .. 2559
            if (gbase + i4 < Q_ * (P_ / 4)) {
                float4 f = gx[i4];
                int row = i4 / (P_ / 4), c4 = i4 % (P_ / 4);
                *(float4*)&sX[row * XSTR + c4 * 4] = f;
            }
        }
    }

    for (int i = t; i < E_ * P_ * H_; i += AB) sW1[i] = W1[i];
    for (int i = t; i < E_ * H_ * H_; i += AB) {
        float v = W2[i];
        sW2[i] = v;
        int e = i / (H_ * H_), r = i % (H_ * H_);
        int hh = r / H_, j = r % H_;
        sW2T[e * H_ * H_ + j * H_ + hh] = v;
    }
    for (int i = t; i < E_ * H_; i += AB) {
        sB1[i] = b1[i];
        sB2[i] = b2[i];
        sW3[i] = W3[i];
    }
    if (t < E_) sB3[t] = b3[t];
    __syncthreads();
    if (!valid) return;

    // stable local rank: # of earlier same-key atoms in this block
    int lr = 0;
    {
        int j = 0;
        #pragma unroll 4
        for (; j + 4 <= t; j += 4) {
            lr += (skey[j]     == key);
            lr += (skey[j + 1] == key);
            lr += (skey[j + 2] == key);
            lr += (skey[j + 3] == key);
        }
        for (; j < t; j++) lr += (skey[j] == key);
    }
    int pos = kb + hb + lr;

    int e = a / QE_;
    const float*  w1  = sW1  + e * P_ * H_;   // [P][H]
    const float*  w2  = sW2  + e * H_ * H_;   // [h][j]
    const float*  w2t = sW2T + e * H_ * H_;   // [j][h]
    const float*  w3  = sW3  + e * H_;

    // ---- layer 1 (packed h-pairs): h12[h2] += (x,x) * W1[p][2h2..2h2+1] ----
    unsigned long long h12[H_ / 2];
    #pragma unroll
    for (int h2 = 0; h2 < H_ / 2; h2++)
        h12[h2] = *(const unsigned long long*)&sB1[e * H_ + 2 * h2];

    const float* xrow = sX + t * XSTR;
    #pragma unroll 2
    for (int p4 = 0; p4 < P_ / 4; p4++) {
        float4 x = *(const float4*)(xrow + p4 * 4);
        float xs[4] = {x.x, x.y, x.z, x.w};
        #pragma unroll
        for (int pp = 0; pp < 4; pp++) {
            unsigned long long x2 = pk2(xs[pp], xs[pp]);
            const float* w1p = w1 + (p4 * 4 + pp) * H_;
            #pragma unroll
            for (int k = 0; k < H_ / 4; k++) {
                ulonglong2 w = *(const ulonglong2*)(w1p + k * 4);
                h12[2 * k]     = fma2(x2, w.x, h12[2 * k]);
                h12[2 * k + 1] = fma2(x2, w.y, h12[2 * k + 1]);
            }
        }
    }
    float h1[H_];
    #pragma unroll
    for (int h2 = 0; h2 < H_ / 2; h2++) {
        float va, vb;
        upk2(h12[h2], va, vb);
        h1[2 * h2]     = tanh_fast(va);
        h1[2 * h2 + 1] = tanh_fast(vb);
    }

    // ---- layer 2 (scalar, W2T float4) ----
    float g2[H_];
    #pragma unroll
    for (int j = 0; j < H_; j++) {
        float s = sB2[e * H_ + j];
        #pragma unroll
        for (int h4 = 0; h4 < H_ / 4; h4++) {
            float4 w = *(const float4*)(w2t + j * H_ + h4 * 4);
            s = fmaf(h1[h4 * 4],     w.x, s);
            s = fmaf(h1[h4 * 4 + 1], w.y, s);
            s = fmaf(h1[h4 * 4 + 2], w.z, s);
            s = fmaf(h1[h4 * 4 + 3], w.w, s);
        }
        g2[j] = tanh_fast(s);
    }

    // ---- layer 3 fwd + backward seed ----
    float en = sB3[e];
    #pragma unroll
    for (int j = 0; j < H_; j++) {
        float v = g2[j];
        en = fmaf(v, w3[j], en);
        g2[j] = w3[j] * (1.0f - v * v);
    }
    atomicAdd(&energy[key], en);

    // ---- g1 (scalar, W2 float4), overwrites h1; then pack into g12 ----
    #pragma unroll
    for (int h = 0; h < H_; h++) {
        float s = 0.0f;
        #pragma unroll
        for (int j4 = 0; j4 < H_ / 4; j4++) {
            float4 w = *(const float4*)(w2 + h * H_ + j4 * 4);
            s = fmaf(w.x, g2[j4 * 4],     s);
            s = fmaf(w.y, g2[j4 * 4 + 1], s);
            s = fmaf(w.z, g2[j4 * 4 + 2], s);
            s = fmaf(w.w, g2[j4 * 4 + 3], s);
        }
        h1[h] = s * (1.0f - h1[h] * h1[h]);
    }
    unsigned long long g12[H_ / 2];
    #pragma unroll
    for (int h2 = 0; h2 < H_ / 2; h2++)
        g12[h2] = pk2(h1[2 * h2], h1[2 * h2 + 1]);

    // ---- -dE/dx (packed): per p, chain 10 FFMA2 then horizontal add ----
    float4* dst = (float4*)(g_dE + (size_t)pos * P_);
    #pragma unroll 2
    for (int p4 = 0; p4 < P_ / 4; p4++) {
        float os[4];
        #pragma unroll
        for (int pp = 0; pp < 4; pp++) {
            const float* w1p = w1 + (p4 * 4 + pp) * H_;
            unsigned long long acc = 0ULL;   // (0.0f, 0.0f)
            #pragma unroll
            for (int k = 0; k < H_ / 4; k++) {
                ulonglong2 w = *(const ulonglong2*)(w1p + k * 4);
                acc = fma2(w.x, g12[2 * k],     acc);
                acc = fma2(w.y, g12[2 * k + 1], acc);
            }
            float va, vb;
            upk2(acc, va, vb);
            os[pp] = -(va + vb);
        }
        float4 o;
        o.x = os[0]; o.y = os[1]; o.z = os[2]; o.w = os[3];
        dst[p4] = o;
    }
}

// ---------------------------------------------------------------------------
// Sparse COO transpose-matvec (R10-profiled form): one int4-group/thread,
// __ldcs streaming on COO arrays, __ldg on g_dE gathers.
// ---------------------------------------------------------------------------
__global__ void k_scatter(const int4* __restrict__ rows,
                          const int4* __restrict__ cols,
                          const float4* __restrict__ vals,
                          float* __restrict__ force)
{
    int i = blockIdx.x * blockDim.x + threadIdx.x;
    if (i >= NNZ_ / 4) return;
    int4   r = __ldcs(&rows[i]);
    int4   c = __ldcs(&cols[i]);
    float4 v = __ldcs(&vals[i]);
    float d0 = __ldg(&g_dE[r.x]);
    float d1 = __ldg(&g_dE[r.y]);
    float d2 = __ldg(&g_dE[r.z]);
    float d3 = __ldg(&g_dE[r.w]);
    atomicAdd(&force[c.x], v.x * d0);
    atomicAdd(&force[c.y], v.y * d1);
    atomicAdd(&force[c.z], v.z * d2);
    atomicAdd(&force[c.w], v.w * d3);
}

// ---------------------------------------------------------------------------
extern "C" void kernel_launch(void* const* d_in, const int* in_sizes, int n_in,
                              void* d_out, int out_size)
{
    const float* fps       = (const float*)d_in[0];
    const float* W1        = (const float*)d_in[1];
    const float* b1        = (const float*)d_in[2];
    const float* W2        = (const float*)d_in[3];
    const float* b2        = (const float*)d_in[4];
    const float* W3        = (const float*)d_in[5];
    const float* b3        = (const float*)d_in[6];
    const int*   image_idx = (const int*)d_in[7];
    const int*   fp_rows   = (const int*)d_in[8];
    const int*   fp_cols   = (const int*)d_in[9];
    const float* fp_vals   = (const float*)d_in[10];

    float* out    = (float*)d_out;
    float* energy = out;               // [NIMG, 1]
    float* force  = out + NIMG_;       // [Q, 3] flattened

    const int sx_bytes = AB * XSTR * (int)sizeof(float);   // 45056
    cudaFuncSetAttribute(k_mlp, cudaFuncAttributeMaxDynamicSharedMemorySize,
                         sx_bytes);

    k_hist<<<NB, AB>>>(image_idx, out, out_size);
    k_scan_blocks<<<NIMG_, NB>>>();
    k_scan_keys<<<1, 1024>>>();

    k_mlp<<<NB, AB, sx_bytes>>>(fps, W1, b1, W2, b2, W3, b3, image_idx, energy);

    k_scatter<<<(NNZ_ / 4 + 255) / 256, 256>>>(
        (const int4*)fp_rows, (const int4*)fp_cols, (const float4*)fp_vals, force);
}

// round 16
// speedup vs baseline: 1.0109x; 1.0109x over previous
#include <cuda_runtime.h>

// Problem constants (fixed shapes from reference_code)
#define E_    3
#define QE_   60000
#define P_    40
#define H_    20
#define NIMG_ 1800
#define Q_    (E_ * QE_)        // 180000 atoms
#define NNZ_  14400000
#define AB    256               // atoms per block
#define NB    704               // ceil(Q_/AB)

// Scratch (static device globals — sanctioned)
__device__ float g_dE[(size_t)Q_ * P_];        // NEGATED dE/dFP, sorted order, 28.8 MB
__device__ int   g_hist[(size_t)NIMG_ * NB];
__device__ int   g_key_total[NIMG_];
__device__ int   g_key_base[NIMG_];

__device__ __forceinline__ float tanh_fast(float x) {
    float y;
    asm("tanh.approx.f32 %0, %1;" : "=f"(y) : "f"(x));
    return y;
}

// ---- packed f32x2 helpers (Blackwell FFMA2 via PTX) ----
__device__ __forceinline__ unsigned long long pk2(float a, float b) {
    unsigned long long d;
    asm("mov.b64 %0, {%1, %2};" : "=l"(d) : "f"(a), "f"(b));
    return d;
}
__device__ __forceinline__ void upk2(unsigned long long d, float& a, float& b) {
    unsigned x, y;
    asm("mov.b64 {%0, %1}, %2;" : "=r"(x), "=r"(y) : "l"(d));
    a = __uint_as_float(x);
    b = __uint_as_float(y);
}
__device__ __forceinline__ unsigned long long fma2(
    unsigned long long a, unsigned long long b, unsigned long long c) {
    unsigned long long d;
    asm("fma.rn.f32x2 %0, %1, %2, %3;" : "=l"(d) : "l"(a), "l"(b), "l"(c));
    return d;
}

// ---------------------------------------------------------------------------
// Histogram of image_idx, fused with zeroing of the output buffer.
// ---------------------------------------------------------------------------
__global__ void k_hist(const int* __restrict__ idx,
                       float* __restrict__ out, int out_n) {
    __shared__ int h[NIMG_];
    for (int k = threadIdx.x; k < NIMG_; k += blockDim.x) h[k] = 0;

    for (int i = blockIdx.x * AB + threadIdx.x; i < out_n; i += NB * AB)
        out[i] = 0.0f;
    __syncthreads();

    int a = blockIdx.x * AB + threadIdx.x;
    if (a < Q_) atomicAdd(&h[idx[a]], 1);
    __syncthreads();
    for (int k = threadIdx.x; k < NIMG_; k += blockDim.x)
        g_hist[(size_t)k * NB + blockIdx.x] = h[k];
}

// ---------------------------------------------------------------------------
// Per-key exclusive scan over blocks: warp-shuffle 2-level scan.
// ---------------------------------------------------------------------------
__global__ void k_scan_blocks() {
    __shared__ int wsum[22];
    int k = blockIdx.x, t = threadIdx.x;
    int lane = t & 31, w = t >> 5;
    int v = g_hist[(size_t)k * NB + t];
    int s = v;
    #pragma unroll
    for (int o = 1; o < 32; o <<= 1) {
        int x = __shfl_up_sync(0xFFFFFFFFu, s, o);
        if (lane >= o) s += x;
    }
    if (lane == 31) wsum[w] = s;
    __syncthreads();
    if (w == 0) {
        int ws = (lane < 22) ? wsum[lane] : 0;
        #pragma unroll
        for (int o = 1; o < 32; o <<= 1) {
            int x = __shfl_up_sync(0xFFFFFFFFu, ws, o);
            if (lane >= o) ws += x;
        }
        if (lane < 22) wsum[lane] = ws;
    }
    __syncthreads();
    int incl = ((w > 0) ? wsum[w - 1] : 0) + s;
    g_hist[(size_t)k * NB + t] = incl - v;   // exclusive
    if (t == NB - 1) g_key_total[k] = incl;
}

// ---------------------------------------------------------------------------
// Exclusive scan over 1800 key totals (2 elems/thread, shuffle scan).
// ---------------------------------------------------------------------------
__global__ void k_scan_keys() {
    __shared__ int wsum[32];
    int t = threadIdx.x, lane = t & 31, w = t >> 5;
    int i0 = 2 * t, i1 = 2 * t + 1;
    int v0 = (i0 < NIMG_) ? g_key_total[i0] : 0;
    int v1 = (i1 < NIMG_) ? g_key_total[i1] : 0;
    int p = v0 + v1, s = p;
    #pragma unroll
    for (int o = 1; o < 32; o <<= 1) {
        int x = __shfl_up_sync(0xFFFFFFFFu, s, o);
        if (lane >= o) s += x;
    }
    if (lane == 31) wsum[w] = s;
    __syncthreads();
    if (w == 0) {
        int ws = wsum[lane];
        #pragma unroll
        for (int o = 1; o < 32; o <<= 1) {
            int x = __shfl_up_sync(0xFFFFFFFFu, ws, o);
            if (lane >= o) ws += x;
        }
        wsum[lane] = ws;
    }
    __syncthreads();
    int excl = ((w > 0) ? wsum[w - 1] : 0) + s - p;
    if (i0 < NIMG_) g_key_base[i0] = excl;
    if (i1 < NIMG_) g_key_base[i1] = excl + v0;
}

// ---------------------------------------------------------------------------
// Fused: stable rank + MLP fwd + input-grad + energy scatter.
// f32x2 (FFMA2) packed math on the P×H GEMVs; dual-layout W2/W2T in smem;
// divergent pos-gathers hoisted above weight staging to hide their latency.
// ---------------------------------------------------------------------------
__global__ void __launch_bounds__(AB, 3) k_mlp(
    const float* __restrict__ fps, const float* __restrict__ W1,
    const float* __restrict__ b1,  const float* __restrict__ W2,
    const float* __restrict__ b2,  const float* __restrict__ W3,
    const float* __restrict__ b3,  const int* __restrict__ idx,
    float* __restrict__ energy)
{
    __shared__ __align__(16) float sW1 [E_ * P_ * H_];   // [P][H] per element
    __shared__ __align__(16) float sW2 [E_ * H_ * H_];   // [h][j]
    __shared__ __align__(16) float sW2T[E_ * H_ * H_];   // [j][h]
    __shared__ __align__(8)  float sB1[E_ * H_];
    __shared__ float sB2[E_ * H_];
    __shared__ float sW3[E_ * H_];
    __shared__ float sB3[E_];
    __shared__ int   skey[AB];

    int t = threadIdx.x;
    int a = blockIdx.x * AB + t;
    bool valid = (a < Q_);

    // early: key + the two divergent pos-gathers (latency hidden by staging)
    int key = valid ? idx[a] : -1;
    skey[t] = key;
    int kb = 0, hb = 0;
    if (valid) {
        kb = g_key_base[key];
        hb = g_hist[(size_t)key * NB + blockIdx.x];
    }

    for (int i = t; i < E_ * P_ * H_; i += AB) sW1[i] = W1[i];
    for (int i = t; i < E_ * H_ * H_; i += AB) {
        float v = W2[i];
        sW2[i] = v;
        int e = i / (H_ * H_), r = i % (H_ * H_);
        int hh = r / H_, j = r % H_;
        sW2T[e * H_ * H_ + j * H_ + hh] = v;
    }
    for (int i = t; i < E_ * H_; i += AB) {
        sB1[i] = b1[i];
        sB2[i] = b2[i];
        sW3[i] = W3[i];
    }
    if (t < E_) sB3[t] = b3[t];
    __syncthreads();
    if (!valid) return;

    // stable local rank: # of earlier same-key atoms in this block
    int lr = 0;
    {
        int j = 0;
        #pragma unroll 4
        for (; j + 4 <= t; j += 4) {
            lr += (skey[j]     == key);
            lr += (skey[j + 1] == key);
            lr += (skey[j + 2] == key);
            lr += (skey[j + 3] == key);
        }
        for (; j < t; j++) lr += (skey[j] == key);
    }
    int pos = kb + hb + lr;

    int e = a / QE_;
    const float*  w1  = sW1  + e * P_ * H_;   // [P][H]
    const float*  w2  = sW2  + e * H_ * H_;   // [h][j]
    const float*  w2t = sW2T + e * H_ * H_;   // [j][h]
    const float*  w3  = sW3  + e * H_;

    // ---- layer 1 (packed h-pairs): h12[h2] += (x,x) * W1[p][2h2..2h2+1] ----
    unsigned long long h12[H_ / 2];
    #pragma unroll
    for (int h2 = 0; h2 < H_ / 2; h2++)
        h12[h2] = *(const unsigned long long*)&sB1[e * H_ + 2 * h2];

    const float4* xrow = (const float4*)(fps + (size_t)a * P_);
    #pragma unroll 2
    for (int p4 = 0; p4 < P_ / 4; p4++) {
        float4 x = xrow[p4];
        float xs[4] = {x.x, x.y, x.z, x.w};
        #pragma unroll
        for (int pp = 0; pp < 4; pp++) {
            unsigned long long x2 = pk2(xs[pp], xs[pp]);
            const float* w1p = w1 + (p4 * 4 + pp) * H_;
            #pragma unroll
            for (int k = 0; k < H_ / 4; k++) {
                ulonglong2 w = *(const ulonglong2*)(w1p + k * 4);
                h12[2 * k]     = fma2(x2, w.x, h12[2 * k]);
                h12[2 * k + 1] = fma2(x2, w.y, h12[2 * k + 1]);
            }
        }
    }
    float h1[H_];
    #pragma unroll
    for (int h2 = 0; h2 < H_ / 2; h2++) {
        float va, vb;
        upk2(h12[h2], va, vb);
        h1[2 * h2]     = tanh_fast(va);
        h1[2 * h2 + 1] = tanh_fast(vb);
    }

    // ---- layer 2 (scalar, W2T float4) ----
    float g2[H_];
    #pragma unroll
    for (int j = 0; j < H_; j++) {
        float s = sB2[e * H_ + j];
        #pragma unroll
        for (int h4 = 0; h4 < H_ / 4; h4++) {
            float4 w = *(const float4*)(w2t + j * H_ + h4 * 4);
            s = fmaf(h1[h4 * 4],     w.x, s);
            s = fmaf(h1[h4 * 4 + 1], w.y, s);
            s = fmaf(h1[h4 * 4 + 2], w.z, s);
            s = fmaf(h1[h4 * 4 + 3], w.w, s);
        }
        g2[j] = tanh_fast(s);
    }

    // ---- layer 3 fwd + backward seed ----
    float en = sB3[e];
    #pragma unroll
    for (int j = 0; j < H_; j++) {
        float v = g2[j];
        en = fmaf(v, w3[j], en);
        g2[j] = w3[j] * (1.0f - v * v);
    }
    atomicAdd(&energy[key], en);

    // ---- g1 (scalar, W2 float4), overwrites h1; then pack into g12 ----
    #pragma unroll
    for (int h = 0; h < H_; h++) {
        float s = 0.0f;
        #pragma unroll
        for (int j4 = 0; j4 < H_ / 4; j4++) {
            float4 w = *(const float4*)(w2 + h * H_ + j4 * 4);
            s = fmaf(w.x, g2[j4 * 4],     s);
            s = fmaf(w.y, g2[j4 * 4 + 1], s);
            s = fmaf(w.z, g2[j4 * 4 + 2], s);
            s = fmaf(w.w, g2[j4 * 4 + 3], s);
        }
        h1[h] = s * (1.0f - h1[h] * h1[h]);
    }
    unsigned long long g12[H_ / 2];
    #pragma unroll
    for (int h2 = 0; h2 < H_ / 2; h2++)
        g12[h2] = pk2(h1[2 * h2], h1[2 * h2 + 1]);

    // ---- -dE/dx (packed): per p, chain 10 FFMA2 then horizontal add ----
    float4* dst = (float4*)(g_dE + (size_t)pos * P_);
    #pragma unroll 2
    for (int p4 = 0; p4 < P_ / 4; p4++) {
        float os[4];
        #pragma unroll
        for (int pp = 0; pp < 4; pp++) {
            const float* w1p = w1 + (p4 * 4 + pp) * H_;
            unsigned long long acc = 0ULL;   // (0.0f, 0.0f)
            #pragma unroll
            for (int k = 0; k < H_ / 4; k++) {
                ulonglong2 w = *(const ulonglong2*)(w1p + k * 4);
                acc = fma2(w.x, g12[2 * k],     acc);
                acc = fma2(w.y, g12[2 * k + 1], acc);
            }
            float va, vb;
            upk2(acc, va, vb);
            os[pp] = -(va + vb);
        }
        float4 o;
        o.x = os[0]; o.y = os[1]; o.z = os[2]; o.w = os[3];
        dst[p4] = o;
    }
}

// ---------------------------------------------------------------------------
// Sparse COO transpose-matvec (profiled at the L2 sector floor): one
// int4-group/thread, __ldcs streaming on COO arrays, __ldg on g_dE gathers.
// ---------------------------------------------------------------------------
__global__ void k_scatter(const int4* __restrict__ rows,
                          const int4* __restrict__ cols,
                          const float4* __restrict__ vals,
                          float* __restrict__ force)
{
    int i = blockIdx.x * blockDim.x + threadIdx.x;
    if (i >= NNZ_ / 4) return;
    int4   r = __ldcs(&rows[i]);
    int4   c = __ldcs(&cols[i]);
    float4 v = __ldcs(&vals[i]);
    float d0 = __ldg(&g_dE[r.x]);
    float d1 = __ldg(&g_dE[r.y]);
    float d2 = __ldg(&g_dE[r.z]);
    float d3 = __ldg(&g_dE[r.w]);
    atomicAdd(&force[c.x], v.x * d0);
    atomicAdd(&force[c.y], v.y * d1);
    atomicAdd(&force[c.z], v.z * d2);
    atomicAdd(&force[c.w], v.w * d3);
}

// ---------------------------------------------------------------------------
extern "C" void kernel_launch(void* const* d_in, const int* in_sizes, int n_in,
                              void* d_out, int out_size)
{
    const float* fps       = (const float*)d_in[0];
    const float* W1        = (const float*)d_in[1];
    const float* b1        = (const float*)d_in[2];
    const float* W2        = (const float*)d_in[3];
    const float* b2        = (const float*)d_in[4];
    const float* W3        = (const float*)d_in[5];
    const float* b3        = (const float*)d_in[6];
    const int*   image_idx = (const int*)d_in[7];
    const int*   fp_rows   = (const int*)d_in[8];
    const int*   fp_cols   = (const int*)d_in[9];
    const float* fp_vals   = (const float*)d_in[10];

    float* out    = (float*)d_out;
    float* energy = out;               // [NIMG, 1]
    float* force  = out + NIMG_;       // [Q, 3] flattened

    k_hist<<<NB, AB>>>(image_idx, out, out_size);
    k_scan_blocks<<<NIMG_, NB>>>();
    k_scan_keys<<<1, 1024>>>();

    k_mlp<<<NB, AB>>>(fps, W1, b1, W2, b2, W3, b3, image_idx, energy);

    k_scatter<<<(NNZ_ / 4 + 255) / 256, 256>>>(
        (const int4*)fp_rows, (const int4*)fp_cols, (const float4*)fp_vals, force);
}

// round 17
// speedup vs baseline: 1.0125x; 1.0016x over previous
#include <cuda_runtime.h>

// Problem constants (fixed shapes from reference_code)
#define E_    3
#define QE_   60000
#define P_    40
#define H_    20
#define NIMG_ 1800
#define Q_    (E_ * QE_)        // 180000 atoms
#define NNZ_  14400000
#define AB    256               // atoms per block
#define NB    704               // ceil(Q_/AB)

// Scratch (static device globals — sanctioned)
__device__ float g_dE[(size_t)Q_ * P_];        // NEGATED dE/dFP, sorted order, 28.8 MB
__device__ int   g_hist[(size_t)NIMG_ * NB];
__device__ int   g_key_total[NIMG_];
__device__ int   g_key_base[NIMG_];

__device__ __forceinline__ float tanh_fast(float x) {
    float y;
    asm("tanh.approx.f32 %0, %1;" : "=f"(y) : "f"(x));
    return y;
}

// ---- packed f32x2 helpers (Blackwell FFMA2 via PTX) ----
__device__ __forceinline__ unsigned long long pk2(float a, float b) {
    unsigned long long d;
    asm("mov.b64 %0, {%1, %2};" : "=l"(d) : "f"(a), "f"(b));
    return d;
}
__device__ __forceinline__ void upk2(unsigned long long d, float& a, float& b) {
    unsigned x, y;
    asm("mov.b64 {%0, %1}, %2;" : "=r"(x), "=r"(y) : "l"(d));
    a = __uint_as_float(x);
    b = __uint_as_float(y);
}
__device__ __forceinline__ unsigned long long fma2(
    unsigned long long a, unsigned long long b, unsigned long long c) {
    unsigned long long d;
    asm("fma.rn.f32x2 %0, %1, %2, %3;" : "=l"(d) : "l"(a), "l"(b), "l"(c));
    return d;
}

// ---------------------------------------------------------------------------
// Histogram of image_idx, fused with zeroing of the output buffer.
// ---------------------------------------------------------------------------
__global__ void k_hist(const int* __restrict__ idx,
                       float* __restrict__ out, int out_n) {
    __shared__ int h[NIMG_];
    for (int k = threadIdx.x; k < NIMG_; k += blockDim.x) h[k] = 0;

    for (int i = blockIdx.x * AB + threadIdx.x; i < out_n; i += NB * AB)
        out[i] = 0.0f;
    __syncthreads();

    int a = blockIdx.x * AB + threadIdx.x;
    if (a < Q_) atomicAdd(&h[idx[a]], 1);
    __syncthreads();
    for (int k = threadIdx.x; k < NIMG_; k += blockDim.x)
        g_hist[(size_t)k * NB + blockIdx.x] = h[k];
}

// ---------------------------------------------------------------------------
// Per-key exclusive scan over blocks: warp-shuffle 2-level scan.
// ---------------------------------------------------------------------------
__global__ void k_scan_blocks() {
    __shared__ int wsum[22];
    int k = blockIdx.x, t = threadIdx.x;
    int lane = t & 31, w = t >> 5;
    int v = g_hist[(size_t)k * NB + t];
    int s = v;
    #pragma unroll
    for (int o = 1; o < 32; o <<= 1) {
        int x = __shfl_up_sync(0xFFFFFFFFu, s, o);
        if (lane >= o) s += x;
    }
    if (lane == 31) wsum[w] = s;
    __syncthreads();
    if (w == 0) {
        int ws = (lane < 22) ? wsum[lane] : 0;
        #pragma unroll
        for (int o = 1; o < 32; o <<= 1) {
            int x = __shfl_up_sync(0xFFFFFFFFu, ws, o);
            if (lane >= o) ws += x;
        }
        if (lane < 22) wsum[lane] = ws;
    }
    __syncthreads();
    int incl = ((w > 0) ? wsum[w - 1] : 0) + s;
    g_hist[(size_t)k * NB + t] = incl - v;   // exclusive
    if (t == NB - 1) g_key_total[k] = incl;
}

// ---------------------------------------------------------------------------
// Exclusive scan over 1800 key totals (2 elems/thread, shuffle scan).
// ---------------------------------------------------------------------------
__global__ void k_scan_keys() {
    __shared__ int wsum[32];
    int t = threadIdx.x, lane = t & 31, w = t >> 5;
    int i0 = 2 * t, i1 = 2 * t + 1;
    int v0 = (i0 < NIMG_) ? g_key_total[i0] : 0;
    int v1 = (i1 < NIMG_) ? g_key_total[i1] : 0;
    int p = v0 + v1, s = p;
    #pragma unroll
    for (int o = 1; o < 32; o <<= 1) {
        int x = __shfl_up_sync(0xFFFFFFFFu, s, o);
        if (lane >= o) s += x;
    }
    if (lane == 31) wsum[w] = s;
    __syncthreads();
    if (w == 0) {
        int ws = wsum[lane];
        #pragma unroll
        for (int o = 1; o < 32; o <<= 1) {
            int x = __shfl_up_sync(0xFFFFFFFFu, ws, o);
            if (lane >= o) ws += x;
        }
        wsum[lane] = ws;
    }
    __syncthreads();
    int excl = ((w > 0) ? wsum[w - 1] : 0) + s - p;
    if (i0 < NIMG_) g_key_base[i0] = excl;
    if (i1 < NIMG_) g_key_base[i1] = excl + v0;
}

// ---------------------------------------------------------------------------
// Fused: stable rank + MLP fwd + input-grad + energy scatter.
// f32x2 (FFMA2) packed math on the P×H GEMVs; dual-layout W2/W2T in smem;
// divergent pos-gathers hoisted above weight staging to hide their latency.
// ---------------------------------------------------------------------------
__global__ void __launch_bounds__(AB, 3) k_mlp(
    const float* __restrict__ fps, const float* __restrict__ W1,
    const float* __restrict__ b1,  const float* __restrict__ W2,
    const float* __restrict__ b2,  const float* __restrict__ W3,
    const float* __restrict__ b3,  const int* __restrict__ idx,
    float* __restrict__ energy)
{
    __shared__ __align__(16) float sW1 [E_ * P_ * H_];   // [P][H] per element
    __shared__ __align__(16) float sW2 [E_ * H_ * H_];   // [h][j]
    __shared__ __align__(16) float sW2T[E_ * H_ * H_];   // [j][h]
    __shared__ __align__(8)  float sB1[E_ * H_];
    __shared__ float sB2[E_ * H_];
    __shared__ float sW3[E_ * H_];
    __shared__ float sB3[E_];
    __shared__ int   skey[AB];

    int t = threadIdx.x;
    int a = blockIdx.x * AB + t;
    bool valid = (a < Q_);

    // early: key + the two divergent pos-gathers (latency hidden by staging)
    int key = valid ? idx[a] : -1;
    skey[t] = key;
    int kb = 0, hb = 0;
    if (valid) {
        kb = g_key_base[key];
        hb = g_hist[(size_t)key * NB + blockIdx.x];
    }

    for (int i = t; i < E_ * P_ * H_; i += AB) sW1[i] = W1[i];
    for (int i = t; i < E_ * H_ * H_; i += AB) {
        float v = W2[i];
        sW2[i] = v;
        int e = i / (H_ * H_), r = i % (H_ * H_);
        int hh = r / H_, j = r % H_;
        sW2T[e * H_ * H_ + j * H_ + hh] = v;
    }
    for (int i = t; i < E_ * H_; i += AB) {
        sB1[i] = b1[i];
        sB2[i] = b2[i];
        sW3[i] = W3[i];
    }
    if (t < E_) sB3[t] = b3[t];
    __syncthreads();
    if (!valid) return;

    // stable local rank: # of earlier same-key atoms in this block
    int lr = 0;
    {
        int j = 0;
        #pragma unroll 4
        for (; j + 4 <= t; j += 4) {
            lr += (skey[j]     == key);
            lr += (skey[j + 1] == key);
            lr += (skey[j + 2] == key);
            lr += (skey[j + 3] == key);
        }
        for (; j < t; j++) lr += (skey[j] == key);
    }
    int pos = kb + hb + lr;

    int e = a / QE_;
    const float*  w1  = sW1  + e * P_ * H_;   // [P][H]
    const float*  w2  = sW2  + e * H_ * H_;   // [h][j]
    const float*  w2t = sW2T + e * H_ * H_;   // [j][h]
    const float*  w3  = sW3  + e * H_;

    // ---- layer 1 (packed h-pairs): h12[h2] += (x,x) * W1[p][2h2..2h2+1] ----
    unsigned long long h12[H_ / 2];
    #pragma unroll
    for (int h2 = 0; h2 < H_ / 2; h2++)
        h12[h2] = *(const unsigned long long*)&sB1[e * H_ + 2 * h2];

    const float4* xrow = (const float4*)(fps + (size_t)a * P_);
    #pragma unroll 2
    for (int p4 = 0; p4 < P_ / 4; p4++) {
        float4 x = xrow[p4];
        float xs[4] = {x.x, x.y, x.z, x.w};
        #pragma unroll
        for (int pp = 0; pp < 4; pp++) {
            unsigned long long x2 = pk2(xs[pp], xs[pp]);
            const float* w1p = w1 + (p4 * 4 + pp) * H_;
            #pragma unroll
            for (int k = 0; k < H_ / 4; k++) {
                ulonglong2 w = *(const ulonglong2*)(w1p + k * 4);
                h12[2 * k]     = fma2(x2, w.x, h12[2 * k]);
                h12[2 * k + 1] = fma2(x2, w.y, h12[2 * k + 1]);
            }
        }
    }
    float h1[H_];
    #pragma unroll
    for (int h2 = 0; h2 < H_ / 2; h2++) {
        float va, vb;
        upk2(h12[h2], va, vb);
        h1[2 * h2]     = tanh_fast(va);
        h1[2 * h2 + 1] = tanh_fast(vb);
    }

    // ---- layer 2 (scalar, W2T float4) ----
    float g2[H_];
    #pragma unroll
    for (int j = 0; j < H_; j++) {
        float s = sB2[e * H_ + j];
        #pragma unroll
        for (int h4 = 0; h4 < H_ / 4; h4++) {
            float4 w = *(const float4*)(w2t + j * H_ + h4 * 4);
            s = fmaf(h1[h4 * 4],     w.x, s);
            s = fmaf(h1[h4 * 4 + 1], w.y, s);
            s = fmaf(h1[h4 * 4 + 2], w.z, s);
            s = fmaf(h1[h4 * 4 + 3], w.w, s);
        }
        g2[j] = tanh_fast(s);
    }

    // ---- layer 3 fwd + backward seed ----
    float en = sB3[e];
    #pragma unroll
    for (int j = 0; j < H_; j++) {
        float v = g2[j];
        en = fmaf(v, w3[j], en);
        g2[j] = w3[j] * (1.0f - v * v);
    }
    atomicAdd(&energy[key], en);

    // ---- g1 (scalar, W2 float4), overwrites h1; then pack into g12 ----
    #pragma unroll
    for (int h = 0; h < H_; h++) {
        float s = 0.0f;
        #pragma unroll
        for (int j4 = 0; j4 < H_ / 4; j4++) {
            float4 w = *(const float4*)(w2 + h * H_ + j4 * 4);
            s = fmaf(w.x, g2[j4 * 4],     s);
            s = fmaf(w.y, g2[j4 * 4 + 1], s);
            s = fmaf(w.z, g2[j4 * 4 + 2], s);
            s = fmaf(w.w, g2[j4 * 4 + 3], s);
        }
        h1[h] = s * (1.0f - h1[h] * h1[h]);
    }
    unsigned long long g12[H_ / 2];
    #pragma unroll
    for (int h2 = 0; h2 < H_ / 2; h2++)
        g12[h2] = pk2(h1[2 * h2], h1[2 * h2 + 1]);

    // ---- -dE/dx (packed): per p, chain 10 FFMA2 then horizontal add ----
    float4* dst = (float4*)(g_dE + (size_t)pos * P_);
    #pragma unroll 2
    for (int p4 = 0; p4 < P_ / 4; p4++) {
        float os[4];
        #pragma unroll
        for (int pp = 0; pp < 4; pp++) {
            const float* w1p = w1 + (p4 * 4 + pp) * H_;
            unsigned long long acc = 0ULL;   // (0.0f, 0.0f)
            #pragma unroll
            for (int k = 0; k < H_ / 4; k++) {
                ulonglong2 w = *(const ulonglong2*)(w1p + k * 4);
                acc = fma2(w.x, g12[2 * k],     acc);
                acc = fma2(w.y, g12[2 * k + 1], acc);
            }
            float va, vb;
            upk2(acc, va, vb);
            os[pp] = -(va + vb);
        }
        float4 o;
        o.x = os[0]; o.y = os[1]; o.z = os[2]; o.w = os[3];
        dst[p4] = o;
    }
}

// ---------------------------------------------------------------------------
// Sparse COO transpose-matvec (profiled at the L2 sector floor): one
// int4-group/thread, __ldcs streaming on COO arrays, __ldg on g_dE gathers.
// ---------------------------------------------------------------------------
__global__ void k_scatter(const int4* __restrict__ rows,
                          const int4* __restrict__ cols,
                          const float4* __restrict__ vals,
                          float* __restrict__ force)
{
    int i = blockIdx.x * blockDim.x + threadIdx.x;
    if (i >= NNZ_ / 4) return;
    int4   r = __ldcs(&rows[i]);
    int4   c = __ldcs(&cols[i]);
    float4 v = __ldcs(&vals[i]);
    float d0 = __ldg(&g_dE[r.x]);
    float d1 = __ldg(&g_dE[r.y]);
    float d2 = __ldg(&g_dE[r.z]);
    float d3 = __ldg(&g_dE[r.w]);
    atomicAdd(&force[c.x], v.x * d0);
    atomicAdd(&force[c.y], v.y * d1);
    atomicAdd(&force[c.z], v.z * d2);
    atomicAdd(&force[c.w], v.w * d3);
}

// ---------------------------------------------------------------------------
extern "C" void kernel_launch(void* const* d_in, const int* in_sizes, int n_in,
                              void* d_out, int out_size)
{
    const float* fps       = (const float*)d_in[0];
    const float* W1        = (const float*)d_in[1];
    const float* b1        = (const float*)d_in[2];
    const float* W2        = (const float*)d_in[3];
    const float* b2        = (const float*)d_in[4];
    const float* W3        = (const float*)d_in[5];
    const float* b3        = (const float*)d_in[6];
    const int*   image_idx = (const int*)d_in[7];
    const int*   fp_rows   = (const int*)d_in[8];
    const int*   fp_cols   = (const int*)d_in[9];
    const float* fp_vals   = (const float*)d_in[10];

    float* out    = (float*)d_out;
    float* energy = out;               // [NIMG, 1]
    float* force  = out + NIMG_;       // [Q, 3] flattened

    k_hist<<<NB, AB>>>(image_idx, out, out_size);
    k_scan_blocks<<<NIMG_, NB>>>();
    k_scan_keys<<<1, 1024>>>();

    k_mlp<<<NB, AB>>>(fps, W1, b1, W2, b2, W3, b3, image_idx, energy);

    k_scatter<<<(NNZ_ / 4 + 255) / 256, 256>>>(
        (const int4*)fp_rows, (const int4*)fp_cols, (const float4*)fp_vals, force);
}